// round 15
// baseline (speedup 1.0000x reference)
#include <cuda_runtime.h>
#include <cuda_fp16.h>
#include <math.h>
#include <stdint.h>

// ---------------- problem constants ----------------
#define LSEQ 512
#define BB   8
#define EE   1024
#define HH   16
#define HD   64
#define NLAY 2
#define DFF  4096
#define MROWS (LSEQ*BB)          // 4096
#define BHN  (BB*HH)             // 128
#define QSZ  ((size_t)BHN*LSEQ*HD)
#define PT_ELEMS ((size_t)LSEQ*LSEQ*HD)

// ---------------- scratch ----------------
__device__ uint4  g_PTh [PT_ELEMS/8];
__device__ uint4  g_PTt [PT_ELEMS/8];
__device__ uint4  g_QKVh[3*QSZ/8];
__device__ uint4  g_Sh  [(size_t)BHN*LSEQ*LSEQ/8];
__device__ uint4  g_Wh  [(size_t)BHN*LSEQ*LSEQ/8];
__device__ uint4  g_AOh [(size_t)BHN*LSEQ*HD/8];
__device__ uint4  g_ALh [(size_t)MROWS*EE/8];
__device__ uint4  g_Yh  [(size_t)MROWS*EE/8];
__device__ float4 g_X14 [(size_t)MROWS*EE/4];
__device__ uint4  g_X1h [(size_t)MROWS*EE/8];
__device__ float4 g_X4  [(size_t)MROWS*EE/4];
__device__ uint4  g_Xh  [(size_t)MROWS*EE/8];
__device__ uint4  g_Hh  [(size_t)MROWS*DFF/8];
__device__ uint4  g_Wih [(size_t)NLAY*3*EE*EE/8];
__device__ uint4  g_Woh [(size_t)NLAY*EE*EE/8];
__device__ uint4  g_W1h [(size_t)NLAY*DFF*EE/8];
__device__ uint4  g_W2h [(size_t)NLAY*EE*DFF/8];

__device__ __forceinline__ float gelu_exact(float x) {
    return 0.5f * x * (1.0f + erff(x * 0.70710678118654752f));
}
__device__ __forceinline__ void cp16(uint32_t saddr, const void* gaddr) {
    asm volatile("cp.async.cg.shared.global [%0], [%1], 16;\n"
                 :: "r"(saddr), "l"(gaddr));
}
__device__ __forceinline__ void cp_commit() {
    asm volatile("cp.async.commit_group;\n");
}
template<int N>
__device__ __forceinline__ void cp_wait() {
    asm volatile("cp.async.wait_group %0;\n" :: "n"(N));
}
__device__ __forceinline__ uint32_t smem_u32(const void* p) {
    uint32_t a;
    asm("{ .reg .u64 t; cvta.to.shared.u64 t, %1; cvt.u32.u64 %0, t; }"
        : "=r"(a) : "l"(p));
    return a;
}
__device__ __forceinline__ void ldsm_x4(uint32_t& r0, uint32_t& r1,
                                        uint32_t& r2, uint32_t& r3, uint32_t saddr)
{
    asm volatile("ldmatrix.sync.aligned.m8n8.x4.shared.b16 {%0,%1,%2,%3}, [%4];"
                 : "=r"(r0), "=r"(r1), "=r"(r2), "=r"(r3) : "r"(saddr));
}
__device__ __forceinline__ void mma_16816(float* acc, const uint32_t* a, const uint32_t* b)
{
    asm volatile(
        "mma.sync.aligned.m16n8k16.row.col.f32.f16.f16.f32 "
        "{%0,%1,%2,%3}, {%4,%5,%6,%7}, {%8,%9}, {%0,%1,%2,%3};\n"
        : "+f"(acc[0]), "+f"(acc[1]), "+f"(acc[2]), "+f"(acc[3])
        : "r"(a[0]), "r"(a[1]), "r"(a[2]), "r"(a[3]), "r"(b[0]), "r"(b[1]));
}

// ---------------- FP16 tensor-core GEMM (NT), cp.async 3-stage, BK=64 ----------------
// EPI: 0 fp32 C (ACCUM opt); 1 +bias fp32 C; 2 +bias,gelu -> half auxh;
//      3 qkv split half -> auxh; 4 read half C, add, half -> auxh [l,b,e];
//      5 plain half -> C-as-half; 6 +bias, half -> C-as-half (sCz FLOAT units).
template<int BM, int BN, int WM, int WN, int EPI, bool ACCUM>
__global__ void __launch_bounds__((BM/WM)*(BN/WN)*32, 2)
hgemm(const __half* __restrict__ A, int lda, long long sAz,
      const __half* __restrict__ B, int ldb, long long sBz,
      float* __restrict__ C, int ldc, long long sCz,
      const float* __restrict__ bias, __half* __restrict__ auxh,
      int M, int N, int K)
{
    constexpr int BK = 64;
    constexpr int WARPS_M = BM / WM;
    constexpr int WARPS_N = BN / WN;
    constexpr int THREADS = WARPS_M * WARPS_N * 32;
    constexpr int LDSA = BK + 8;            // 72 halves = 144B rows; conflict-free
    constexpr int A_HALVES = BM * LDSA;
    constexpr int B_HALVES = BN * LDSA;
    constexpr int STAGE_HALVES = A_HALVES + B_HALVES;
    constexpr int NSTAGE = 3;
    constexpr int MI = WM / 16;
    constexpr int NI = WN / 8;

    extern __shared__ __half smem[];

    A += (long long)blockIdx.z * sAz;
    B += (long long)blockIdx.z * sBz;
    C += (long long)blockIdx.z * sCz;

    const int bm = blockIdx.y * BM;
    const int bn = blockIdx.x * BN;
    const int tid  = threadIdx.x;
    const int wid  = tid >> 5;
    const int lane = tid & 31;
    const int wm = (wid / WARPS_N) * WM;
    const int wn = (wid % WARPS_N) * WN;
    const int g = lane >> 2;
    const int c = lane & 3;

    uint32_t smem_base = smem_u32(smem);

    const int a_row = (lane & 15);
    const int a_kof = (lane >> 4) << 3;
    const int b_row = ((lane >> 4) << 3) + (lane & 7);
    const int b_kof = ((lane >> 3) & 1) << 3;

    float acc[MI][NI][4];
    #pragma unroll
    for (int mi = 0; mi < MI; mi++)
        #pragma unroll
        for (int ni = 0; ni < NI; ni++)
            #pragma unroll
            for (int r = 0; r < 4; r++) acc[mi][ni][r] = 0.f;

    const int nIter = K / BK;

    auto load_tiles = [&](int stage, int k0) {
        uint32_t sA = smem_base + (uint32_t)(stage * STAGE_HALVES) * 2u;
        uint32_t sB = sA + (uint32_t)A_HALVES * 2u;
        #pragma unroll
        for (int i = tid; i < BM * (BK/8); i += THREADS) {
            int row = i / (BK/8);
            int kc  = (i % (BK/8)) * 8;
            cp16(sA + (uint32_t)(row * LDSA + kc) * 2u,
                 A + (size_t)(bm + row) * lda + k0 + kc);
        }
        #pragma unroll
        for (int i = tid; i < BN * (BK/8); i += THREADS) {
            int row = i / (BK/8);
            int kc  = (i % (BK/8)) * 8;
            cp16(sB + (uint32_t)(row * LDSA + kc) * 2u,
                 B + (size_t)(bn + row) * ldb + k0 + kc);
        }
        cp_commit();
    };

    load_tiles(0, 0);
    if (nIter > 1) load_tiles(1, BK);

    for (int it = 0; it < nIter; it++) {
        if (it + 2 < nIter) { cp_wait<1>(); } else { cp_wait<0>(); }
        __syncthreads();
        if (it + 2 < nIter) load_tiles((it + 2) % NSTAGE, (it + 2) * BK);

        const uint32_t sAb = smem_base + (uint32_t)((it % NSTAGE) * STAGE_HALVES) * 2u;
        const uint32_t sBb = sAb + (uint32_t)A_HALVES * 2u;

        #pragma unroll
        for (int kk = 0; kk < BK; kk += 16) {
            uint32_t af[MI][4], bf[NI][2];
            #pragma unroll
            for (int mi = 0; mi < MI; mi++) {
                uint32_t addr = sAb + (uint32_t)((wm + mi*16 + a_row) * LDSA
                                                 + kk + a_kof) * 2u;
                ldsm_x4(af[mi][0], af[mi][1], af[mi][2], af[mi][3], addr);
            }
            #pragma unroll
            for (int p = 0; p < NI/2; p++) {
                uint32_t addr = sBb + (uint32_t)((wn + p*16 + b_row) * LDSA
                                                 + kk + b_kof) * 2u;
                ldsm_x4(bf[2*p][0], bf[2*p][1], bf[2*p+1][0], bf[2*p+1][1], addr);
            }
            #pragma unroll
            for (int mi = 0; mi < MI; mi++)
                #pragma unroll
                for (int ni = 0; ni < NI; ni++)
                    mma_16816(acc[mi][ni], af[mi], bf[ni]);
        }
    }

    // ---- epilogue ----
    #pragma unroll
    for (int mi = 0; mi < MI; mi++) {
        #pragma unroll
        for (int ni = 0; ni < NI; ni++) {
            int row = bm + wm + mi*16 + g;
            int col = bn + wn + ni*8 + 2*c;
            float bx = 0.f, by = 0.f;
            if (EPI == 1 || EPI == 2 || EPI == 3 || EPI == 6) {
                bx = bias[col]; by = bias[col+1];
            }
            #pragma unroll
            for (int half_ = 0; half_ < 2; half_++) {
                int r = row + half_*8;
                float vx = acc[mi][ni][half_*2+0];
                float vy = acc[mi][ni][half_*2+1];
                if (EPI == 1 || EPI == 2 || EPI == 3 || EPI == 6) { vx += bx; vy += by; }
                if (EPI == 2) {
                    *(__half2*)(auxh + (size_t)r * ldc + col)
                        = __floats2half2_rn(gelu_exact(vx), gelu_exact(vy));
                    continue;
                }
                if (EPI == 3) {
                    int l = r >> 3, b = r & 7;
                    int which = col >> 10;
                    int e = col & 1023;
                    int h = e >> 6, d = e & 63;
                    int bh = b * HH + h;
                    if (which == 0) { vx *= 0.125f; vy *= 0.125f; }
                    if (which < 2) {
                        __half2* P = (__half2*)(auxh + (size_t)which * QSZ
                                                + ((size_t)bh * LSEQ + l) * HD + d);
                        *P = __floats2half2_rn(vx, vy);
                    } else {
                        __half* Pv = auxh + 2 * QSZ + ((size_t)bh * HD + d) * LSEQ + l;
                        Pv[0]    = __float2half_rn(vx);
                        Pv[LSEQ] = __float2half_rn(vy);
                    }
                    continue;
                }
                if (EPI == 4) {
                    __half2 o2 = *(const __half2*)((const __half*)C
                                                   + (size_t)r * ldc + col);
                    float2 o = __half22float2(o2);
                    int l = blockIdx.z;
                    int b = r >> 4, h = r & 15;   // r = bh
                    __half2* P = (__half2*)(auxh + ((size_t)(l * BB + b) * EE)
                                            + h * HD + col);
                    *P = __floats2half2_rn(vx + o.x, vy + o.y);
                    continue;
                }
                if (EPI == 5 || EPI == 6) {
                    __half* Ch = (__half*)C;
                    *(__half2*)(Ch + (size_t)r * ldc + col)
                        = __floats2half2_rn(vx, vy);
                    continue;
                }
                float2* Cp = (float2*)(C + (size_t)r * ldc + col);
                if (ACCUM) {
                    float2 o = *Cp;
                    vx += o.x; vy += o.y;
                }
                *Cp = make_float2(vx, vy);
            }
        }
    }
}

// ============ fused pt-score accumulate + softmax, BK=64 single-stage ============
__global__ void __launch_bounds__(512, 1)
score_pt_softmax(const __half* __restrict__ Qm, const __half* __restrict__ PT,
                 const __half* __restrict__ S, __half* __restrict__ W)
{
    constexpr int BM = 64, BN = 512, BK = 64, LDSA = 72;
    constexpr int A_HALVES = BM * LDSA;       // 4608
    constexpr int B_HALVES = BN * LDSA;       // 36864
    constexpr int MI = 2, NI = 8, WARPS_N = 8;

    extern __shared__ __half smem[];
    __shared__ float redmx[BM][WARPS_N];
    __shared__ float redsm[BM][WARPS_N];

    const int l  = blockIdx.y;
    const int bm = blockIdx.x * BM;
    const int tid  = threadIdx.x;
    const int wid  = tid >> 5;
    const int lane = tid & 31;
    const int wm = (wid / WARPS_N) * 32;
    const int wn = (wid % WARPS_N) * 64;
    const int wnx = wid % WARPS_N;
    const int g = lane >> 2, c = lane & 3;

    uint32_t smem_base = smem_u32(smem);
    const int a_row = (lane & 15);
    const int a_kof = (lane >> 4) << 3;
    const int b_row = ((lane >> 4) << 3) + (lane & 7);
    const int b_kof = ((lane >> 3) & 1) << 3;

    // single-stage load of the full K=64
    {
        uint32_t sA = smem_base;
        uint32_t sB = sA + (uint32_t)A_HALVES * 2u;
        #pragma unroll
        for (int i = tid; i < BM * (BK/8); i += 512) {     // 512 cp16: 1 per thread
            int row = i >> 3; int kc = (i & 7) * 8;
            cp16(sA + (uint32_t)(row * LDSA + kc) * 2u,
                 Qm + ((size_t)(bm + row) * LSEQ + l) * HD + kc);
        }
        #pragma unroll
        for (int i = tid; i < BN * (BK/8); i += 512) {     // 4096 cp16: 8 per thread
            int row = i >> 3; int kc = (i & 7) * 8;
            cp16(sB + (uint32_t)(row * LDSA + kc) * 2u,
                 PT + ((size_t)l * LSEQ + row) * HD + kc);
        }
        cp_commit();
    }

    float acc[MI][NI][4];
    #pragma unroll
    for (int mi = 0; mi < MI; mi++)
        #pragma unroll
        for (int ni = 0; ni < NI; ni++)
            #pragma unroll
            for (int r = 0; r < 4; r++) acc[mi][ni][r] = 0.f;

    cp_wait<0>();
    __syncthreads();

    const uint32_t sAb = smem_base;
    const uint32_t sBb = sAb + (uint32_t)A_HALVES * 2u;
    #pragma unroll
    for (int kk = 0; kk < BK; kk += 16) {
        uint32_t af[MI][4], bf[NI][2];
        #pragma unroll
        for (int mi = 0; mi < MI; mi++) {
            uint32_t addr = sAb + (uint32_t)((wm + mi*16 + a_row) * LDSA
                                             + kk + a_kof) * 2u;
            ldsm_x4(af[mi][0], af[mi][1], af[mi][2], af[mi][3], addr);
        }
        #pragma unroll
        for (int p = 0; p < NI/2; p++) {
            uint32_t addr = sBb + (uint32_t)((wn + p*16 + b_row) * LDSA
                                             + kk + b_kof) * 2u;
            ldsm_x4(bf[2*p][0], bf[2*p][1], bf[2*p+1][0], bf[2*p+1][1], addr);
        }
        #pragma unroll
        for (int mi = 0; mi < MI; mi++)
            #pragma unroll
            for (int ni = 0; ni < NI; ni++)
                mma_16816(acc[mi][ni], af[mi], bf[ni]);
    }

    // ---- add S (QK^T, half) ----
    #pragma unroll
    for (int mi = 0; mi < MI; mi++)
        #pragma unroll
        for (int half_ = 0; half_ < 2; half_++) {
            int rl = wm + mi*16 + g + half_*8;
            const __half* Sp = S + ((size_t)(bm + rl) * LSEQ + l) * LSEQ;
            #pragma unroll
            for (int ni = 0; ni < NI; ni++) {
                float2 o = __half22float2(
                    *(const __half2*)(Sp + wn + ni*8 + 2*c));
                acc[mi][ni][half_*2+0] += o.x;
                acc[mi][ni][half_*2+1] += o.y;
            }
        }

    // ---- row max ----
    #pragma unroll
    for (int mi = 0; mi < MI; mi++)
        #pragma unroll
        for (int half_ = 0; half_ < 2; half_++) {
            float m = -1e30f;
            #pragma unroll
            for (int ni = 0; ni < NI; ni++) {
                m = fmaxf(m, acc[mi][ni][half_*2+0]);
                m = fmaxf(m, acc[mi][ni][half_*2+1]);
            }
            m = fmaxf(m, __shfl_xor_sync(0xffffffffu, m, 1));
            m = fmaxf(m, __shfl_xor_sync(0xffffffffu, m, 2));
            if (c == 0) redmx[wm + mi*16 + g + half_*8][wnx] = m;
        }
    __syncthreads();

    // ---- exp + row sum ----
    #pragma unroll
    for (int mi = 0; mi < MI; mi++)
        #pragma unroll
        for (int half_ = 0; half_ < 2; half_++) {
            int rl = wm + mi*16 + g + half_*8;
            float m = redmx[rl][0];
            #pragma unroll
            for (int w = 1; w < WARPS_N; w++) m = fmaxf(m, redmx[rl][w]);
            float s = 0.f;
            #pragma unroll
            for (int ni = 0; ni < NI; ni++) {
                float vx = __expf(acc[mi][ni][half_*2+0] - m);
                float vy = __expf(acc[mi][ni][half_*2+1] - m);
                acc[mi][ni][half_*2+0] = vx;
                acc[mi][ni][half_*2+1] = vy;
                s += vx + vy;
            }
            s += __shfl_xor_sync(0xffffffffu, s, 1);
            s += __shfl_xor_sync(0xffffffffu, s, 2);
            if (c == 0) redsm[rl][wnx] = s;
        }
    __syncthreads();

    // ---- scale + write half ----
    #pragma unroll
    for (int mi = 0; mi < MI; mi++)
        #pragma unroll
        for (int half_ = 0; half_ < 2; half_++) {
            int rl = wm + mi*16 + g + half_*8;
            float s = 0.f;
            #pragma unroll
            for (int w = 0; w < WARPS_N; w++) s += redsm[rl][w];
            float inv = 1.0f / s;
            __half* Wp = W + ((size_t)(bm + rl) * LSEQ + l) * LSEQ;
            #pragma unroll
            for (int ni = 0; ni < NI; ni++) {
                *(__half2*)(Wp + wn + ni*8 + 2*c) =
                    __floats2half2_rn(acc[mi][ni][half_*2+0] * inv,
                                      acc[mi][ni][half_*2+1] * inv);
            }
        }
}

// ---------------- fused pt build: PTh[l,s,d] = half(pos+typ), PTt[l,d,s] ----------------
__global__ void pt_build_kernel(const float4* __restrict__ pos,
                                const float4* __restrict__ typ,
                                __half* __restrict__ PTh, __half* __restrict__ PTt)
{
    __shared__ __half tile[64][72];
    int l = blockIdx.x;
    int t = threadIdx.x;   // 256
    for (int st = 0; st < 8; st++) {
        for (int i = t; i < 1024; i += 256) {
            int s = i >> 4, c4 = i & 15;
            size_t idx = (((size_t)l * LSEQ + st*64 + s) * HD >> 2) + c4;
            float4 a = pos[idx], b = typ[idx];
            __half2 h0 = __floats2half2_rn(a.x + b.x, a.y + b.y);
            __half2 h1 = __floats2half2_rn(a.z + b.z, a.w + b.w);
            __half2* ph = (__half2*)(PTh + ((size_t)l * LSEQ + st*64 + s) * HD + c4*4);
            ph[0] = h0; ph[1] = h1;
            *(__half2*)&tile[s][c4*4]     = h0;
            *(__half2*)&tile[s][c4*4 + 2] = h1;
        }
        __syncthreads();
        for (int i = t; i < 64 * 32; i += 256) {
            int d = i >> 5;
            int s2 = (i & 31) * 2;
            __half2 h = __halves2half2(tile[s2][d], tile[s2+1][d]);
            *(__half2*)(PTt + ((size_t)l * HD + d) * LSEQ + st*64 + s2) = h;
        }
        __syncthreads();
    }
}

// ---------------- multi-segment fp32 -> half (one launch for all conversions) ----------------
struct F2HSegs {
    const float4* src[5];
    __half* dst[5];
    int     pfx[6];    // prefix sums of n4 per segment
};
__global__ void f2h_multi_kernel(F2HSegs segs)
{
    int i = blockIdx.x * blockDim.x + threadIdx.x;
    if (i >= segs.pfx[5]) return;
    int s = 0;
    #pragma unroll
    for (int k = 1; k < 5; k++) s += (i >= segs.pfx[k]);
    int j = i - segs.pfx[s];
    float4 x = segs.src[s][j];
    __half2* p = (__half2*)(segs.dst[s] + (size_t)j * 4);
    p[0] = __floats2half2_rn(x.x, x.y);
    p[1] = __floats2half2_rn(x.z, x.w);
}

// ---------------- LN(residual): X fp32 + Y half; exact fp32 out + optional half copy ----------------
__global__ void ln_res_kernel(const float* __restrict__ X, const __half* __restrict__ Yh,
                              const float* __restrict__ g, const float* __restrict__ be,
                              float* __restrict__ O, __half* __restrict__ Oh)
{
    int row = blockIdx.x;
    int t = threadIdx.x;
    const float4* x4 = (const float4*)(X + (size_t)row * EE);
    const __half2* y2 = (const __half2*)(Yh + (size_t)row * EE);
    float4 a = x4[t];
    float2 b0 = __half22float2(y2[t*2]);
    float2 b1 = __half22float2(y2[t*2+1]);
    float4 v = make_float4(a.x+b0.x, a.y+b0.y, a.z+b1.x, a.w+b1.y);
    float s = v.x + v.y + v.z + v.w;
    float q = v.x*v.x + v.y*v.y + v.z*v.z + v.w*v.w;
    __shared__ float sh_s[8], sh_q[8];
    #pragma unroll
    for (int o = 16; o; o >>= 1) {
        s += __shfl_xor_sync(0xffffffffu, s, o);
        q += __shfl_xor_sync(0xffffffffu, q, o);
    }
    int wid = t >> 5, lane = t & 31;
    if (!lane) { sh_s[wid] = s; sh_q[wid] = q; }
    __syncthreads();
    if (t < 32) {
        s = (lane < 8) ? sh_s[lane] : 0.f;
        q = (lane < 8) ? sh_q[lane] : 0.f;
        #pragma unroll
        for (int o = 4; o; o >>= 1) {
            s += __shfl_xor_sync(0xffffffffu, s, o);
            q += __shfl_xor_sync(0xffffffffu, q, o);
        }
        if (!lane) { sh_s[0] = s; sh_q[0] = q; }
    }
    __syncthreads();
    float mean = sh_s[0] * (1.f/EE);
    float var  = sh_q[0] * (1.f/EE) - mean * mean;
    float r = rsqrtf(var + 1e-5f);
    float4 gg = ((const float4*)g)[t];
    float4 bb = ((const float4*)be)[t];
    float4 o;
    o.x = (v.x - mean) * r * gg.x + bb.x;
    o.y = (v.y - mean) * r * gg.y + bb.y;
    o.z = (v.z - mean) * r * gg.z + bb.z;
    o.w = (v.w - mean) * r * gg.w + bb.w;
    ((float4*)(O + (size_t)row * EE))[t] = o;
    if (Oh) {
        __half2* p = (__half2*)(Oh + (size_t)row * EE + t * 4);
        p[0] = __floats2half2_rn(o.x, o.y);
        p[1] = __floats2half2_rn(o.z, o.w);
    }
}

// ---------------- launch ----------------
static void* symv(const void* devSymbol) {
    void* p = nullptr;
    cudaGetSymbolAddress(&p, devSymbol);
    return p;
}

#define SMEM_H128x128 (3 * (128*72 + 128*72) * 2)   // 110592
#define SMEM_H128x64  (3 * (128*72 +  64*72) * 2)   // 82944
#define SMEM_SS       ((64*72 + 512*72) * 2)        // 82944

extern "C" void kernel_launch(void* const* d_in, const int* in_sizes, int n_in,
                              void* d_out, int out_size)
{
    const float* src = (const float*)d_in[0];
    const float* pos = (const float*)d_in[1];
    const float* typ = (const float*)d_in[2];
    const float* Wi  = (const float*)d_in[3];
    const float* bi  = (const float*)d_in[4];
    const float* Wo  = (const float*)d_in[5];
    const float* bo  = (const float*)d_in[6];
    const float* W1  = (const float*)d_in[7];
    const float* b1  = (const float*)d_in[8];
    const float* W2  = (const float*)d_in[9];
    const float* b2  = (const float*)d_in[10];
    const float* g1  = (const float*)d_in[11];
    const float* be1 = (const float*)d_in[12];
    const float* g2  = (const float*)d_in[13];
    const float* be2 = (const float*)d_in[14];
    float* out = (float*)d_out;

    __half* PTh  = (__half*)symv(g_PTh);
    __half* PTt  = (__half*)symv(g_PTt);
    __half* QKVh = (__half*)symv(g_QKVh);
    __half* Q = QKVh, *K = QKVh + QSZ, *Vt = QKVh + 2*QSZ;
    __half* Sh   = (__half*)symv(g_Sh);
    __half* Wh   = (__half*)symv(g_Wh);
    __half* AOh  = (__half*)symv(g_AOh);
    __half* AL   = (__half*)symv(g_ALh);
    __half* Yh   = (__half*)symv(g_Yh);
    float*  X1   = (float*)symv(g_X14);
    __half* X1h  = (__half*)symv(g_X1h);
    float*  X    = (float*)symv(g_X4);
    __half* Xh   = (__half*)symv(g_Xh);
    __half* Hh   = (__half*)symv(g_Hh);
    __half* Wih  = (__half*)symv(g_Wih);
    __half* Woh  = (__half*)symv(g_Woh);
    __half* W1h  = (__half*)symv(g_W1h);
    __half* W2h  = (__half*)symv(g_W2h);

    static bool attrs_done = false;
    if (!attrs_done) {
        cudaFuncSetAttribute(hgemm<128,128,64,32,3,false>,
                             cudaFuncAttributeMaxDynamicSharedMemorySize, SMEM_H128x128);
        cudaFuncSetAttribute(hgemm<128,128,64,32,5,false>,
                             cudaFuncAttributeMaxDynamicSharedMemorySize, SMEM_H128x128);
        cudaFuncSetAttribute(hgemm<128,128,64,32,6,false>,
                             cudaFuncAttributeMaxDynamicSharedMemorySize, SMEM_H128x128);
        cudaFuncSetAttribute(hgemm<128,128,64,32,2,false>,
                             cudaFuncAttributeMaxDynamicSharedMemorySize, SMEM_H128x128);
        cudaFuncSetAttribute(hgemm<128,64,32,32,5,false>,
                             cudaFuncAttributeMaxDynamicSharedMemorySize, SMEM_H128x64);
        cudaFuncSetAttribute(hgemm<128,64,32,32,4,false>,
                             cudaFuncAttributeMaxDynamicSharedMemorySize, SMEM_H128x64);
        cudaFuncSetAttribute(score_pt_softmax,
                             cudaFuncAttributeMaxDynamicSharedMemorySize, SMEM_SS);
        attrs_done = true;
    }

    // one-time conversions / fused pt build
    pt_build_kernel<<<LSEQ, 256>>>((const float4*)pos, (const float4*)typ, PTh, PTt);
    {
        F2HSegs segs;
        int n0 = NLAY*3*EE*EE/4, n1 = NLAY*EE*EE/4,
            n2 = NLAY*DFF*EE/4, n3 = NLAY*EE*DFF/4, n4 = MROWS*EE/4;
        segs.src[0] = (const float4*)Wi;  segs.dst[0] = Wih;
        segs.src[1] = (const float4*)Wo;  segs.dst[1] = Woh;
        segs.src[2] = (const float4*)W1;  segs.dst[2] = W1h;
        segs.src[3] = (const float4*)W2;  segs.dst[3] = W2h;
        segs.src[4] = (const float4*)src; segs.dst[4] = Xh;
        segs.pfx[0] = 0;
        segs.pfx[1] = n0;
        segs.pfx[2] = n0 + n1;
        segs.pfx[3] = n0 + n1 + n2;
        segs.pfx[4] = n0 + n1 + n2 + n3;
        segs.pfx[5] = n0 + n1 + n2 + n3 + n4;
        f2h_multi_kernel<<<(segs.pfx[5] + 255)/256, 256>>>(segs);
    }

    const float* x = src;     // exact residual input
    for (int l = 0; l < NLAY; l++) {
        // 1) QKV GEMM + fused split epilogue -> Q|K [bh,l,d], V [bh,d,s]
        hgemm<128,128,64,32,3,false><<<dim3(24,32,1), 256, SMEM_H128x128>>>(
            Xh, EE, 0, Wih + (size_t)l*3*EE*EE, EE, 0,
            nullptr, 0, 0, bi + (size_t)l*3*EE, QKVh, MROWS, 3*EE, EE);

        // 2) Sh = half(Q @ K^T)  (batched over bh)
        hgemm<128,128,64,32,5,false><<<dim3(4,4,BHN), 256, SMEM_H128x128>>>(
            Q, HD, (long long)LSEQ*HD, K, HD, (long long)LSEQ*HD,
            (float*)Sh, LSEQ, (long long)LSEQ*LSEQ/2, nullptr, nullptr,
            LSEQ, LSEQ, HD);

        // 3+4) fused: Wh = softmax(Sh + Q @ PT^T) per row (single-stage BK=64)
        score_pt_softmax<<<dim3(2, LSEQ), 512, SMEM_SS>>>(Q, PTh, Sh, Wh);

        // 5) AOh = half(Wh @ Vt^T)
        hgemm<128,64,32,32,5,false><<<dim3(1,4,BHN), 256, SMEM_H128x64>>>(
            Wh, LSEQ, (long long)LSEQ*LSEQ, Vt, LSEQ, (long long)HD*LSEQ,
            (float*)AOh, HD, (long long)LSEQ*HD/2, nullptr, nullptr,
            LSEQ, HD, LSEQ);

        // 6) AL[l,b,e] = half(AOh + Wh[:,l,:] @ PTt[l]^T), fused reorder
        hgemm<128,64,32,32,4,false><<<dim3(1,1,LSEQ), 256, SMEM_H128x64>>>(
            Wh, LSEQ*LSEQ, (long long)LSEQ,
            PTt, LSEQ, (long long)HD*LSEQ,
            (float*)AOh, LSEQ*HD, (long long)HD/2,
            nullptr, AL, BHN, HD, LSEQ);

        // 7) Yh = half(AL @ Wo^T + bo)
        hgemm<128,128,64,32,6,false><<<dim3(8,32,1), 256, SMEM_H128x128>>>(
            AL, EE, 0, Woh + (size_t)l*EE*EE, EE, 0,
            (float*)Yh, EE, 0, bo + (size_t)l*EE, nullptr, MROWS, EE, EE);

        // 8) X1 = LN(x + Yh)  (exact) + X1h (half)
        ln_res_kernel<<<MROWS, 256>>>(x, Yh, g1 + (size_t)l*EE, be1 + (size_t)l*EE, X1, X1h);

        // 9) Hh = half(gelu(X1h @ W1^T + b1))
        hgemm<128,128,64,32,2,false><<<dim3(32,32,1), 256, SMEM_H128x128>>>(
            X1h, EE, 0, W1h + (size_t)l*DFF*EE, EE, 0,
            nullptr, DFF, 0, b1 + (size_t)l*DFF, Hh, MROWS, DFF, EE);

        // 10) Yh = half(Hh @ W2^T + b2)
        hgemm<128,128,64,32,6,false><<<dim3(8,32,1), 256, SMEM_H128x128>>>(
            Hh, DFF, 0, W2h + (size_t)l*EE*DFF, DFF, 0,
            (float*)Yh, EE, 0, b2 + (size_t)l*EE, nullptr, MROWS, EE, DFF);

        // 11) next = LN(X1 + Yh); last layer -> d_out
        float*  xo  = (l == NLAY-1) ? out : X;
        __half* xoh = (l == NLAY-1) ? nullptr : Xh;
        ln_res_kernel<<<MROWS, 256>>>(X1, Yh, g2 + (size_t)l*EE, be2 + (size_t)l*EE, xo, xoh);

        x = X;
    }
}

// round 16
// speedup vs baseline: 1.0433x; 1.0433x over previous
#include <cuda_runtime.h>
#include <cuda_fp16.h>
#include <math.h>
#include <stdint.h>

// ---------------- problem constants ----------------
#define LSEQ 512
#define BB   8
#define EE   1024
#define HH   16
#define HD   64
#define NLAY 2
#define DFF  4096
#define MROWS (LSEQ*BB)          // 4096
#define BHN  (BB*HH)             // 128
#define QSZ  ((size_t)BHN*LSEQ*HD)
#define PT_ELEMS ((size_t)LSEQ*LSEQ*HD)

// ---------------- scratch ----------------
__device__ uint4  g_PTh [PT_ELEMS/8];
__device__ uint4  g_PTt [PT_ELEMS/8];
__device__ uint4  g_QKVh[3*QSZ/8];
__device__ uint4  g_Sh  [(size_t)BHN*LSEQ*LSEQ/8];
__device__ uint4  g_Wh  [(size_t)BHN*LSEQ*LSEQ/8];
__device__ uint4  g_AOh [(size_t)BHN*LSEQ*HD/8];
__device__ uint4  g_ALh [(size_t)MROWS*EE/8];
__device__ uint4  g_Yh  [(size_t)MROWS*EE/8];
__device__ float4 g_X14 [(size_t)MROWS*EE/4];
__device__ uint4  g_X1h [(size_t)MROWS*EE/8];
__device__ float4 g_X4  [(size_t)MROWS*EE/4];
__device__ uint4  g_Xh  [(size_t)MROWS*EE/8];
__device__ uint4  g_Hh  [(size_t)MROWS*DFF/8];
__device__ uint4  g_Wih [(size_t)NLAY*3*EE*EE/8];
__device__ uint4  g_Woh [(size_t)NLAY*EE*EE/8];
__device__ uint4  g_W1h [(size_t)NLAY*DFF*EE/8];
__device__ uint4  g_W2h [(size_t)NLAY*EE*DFF/8];

__device__ __forceinline__ float gelu_exact(float x) {
    return 0.5f * x * (1.0f + erff(x * 0.70710678118654752f));
}
__device__ __forceinline__ void cp16(uint32_t saddr, const void* gaddr) {
    asm volatile("cp.async.cg.shared.global [%0], [%1], 16;\n"
                 :: "r"(saddr), "l"(gaddr));
}
__device__ __forceinline__ void cp_commit() {
    asm volatile("cp.async.commit_group;\n");
}
template<int N>
__device__ __forceinline__ void cp_wait() {
    asm volatile("cp.async.wait_group %0;\n" :: "n"(N));
}
__device__ __forceinline__ uint32_t smem_u32(const void* p) {
    uint32_t a;
    asm("{ .reg .u64 t; cvta.to.shared.u64 t, %1; cvt.u32.u64 %0, t; }"
        : "=r"(a) : "l"(p));
    return a;
}
__device__ __forceinline__ void ldsm_x4(uint32_t& r0, uint32_t& r1,
                                        uint32_t& r2, uint32_t& r3, uint32_t saddr)
{
    asm volatile("ldmatrix.sync.aligned.m8n8.x4.shared.b16 {%0,%1,%2,%3}, [%4];"
                 : "=r"(r0), "=r"(r1), "=r"(r2), "=r"(r3) : "r"(saddr));
}
__device__ __forceinline__ void mma_16816(float* acc, const uint32_t* a, const uint32_t* b)
{
    asm volatile(
        "mma.sync.aligned.m16n8k16.row.col.f32.f16.f16.f32 "
        "{%0,%1,%2,%3}, {%4,%5,%6,%7}, {%8,%9}, {%0,%1,%2,%3};\n"
        : "+f"(acc[0]), "+f"(acc[1]), "+f"(acc[2]), "+f"(acc[3])
        : "r"(a[0]), "r"(a[1]), "r"(a[2]), "r"(a[3]), "r"(b[0]), "r"(b[1]));
}

// ---------------- FP16 tensor-core GEMM (NT), cp.async 3-stage, templated BK ----------------
// EPI: 0 fp32 C (ACCUM opt); 1 +bias fp32 C; 2 +bias,gelu -> half auxh;
//      3 qkv split half -> auxh; 4 read half C, add, half -> auxh [l,b,e];
//      5 plain half -> C-as-half; 6 +bias, half -> C-as-half (sCz FLOAT units).
template<int BM, int BN, int WM, int WN, int BK, int EPI, bool ACCUM>
__global__ void __launch_bounds__((BM/WM)*(BN/WN)*32, 2)
hgemm(const __half* __restrict__ A, int lda, long long sAz,
      const __half* __restrict__ B, int ldb, long long sBz,
      float* __restrict__ C, int ldc, long long sCz,
      const float* __restrict__ bias, __half* __restrict__ auxh,
      int M, int N, int K)
{
    constexpr int WARPS_M = BM / WM;
    constexpr int WARPS_N = BN / WN;
    constexpr int THREADS = WARPS_M * WARPS_N * 32;
    constexpr int LDSA = BK + 8;            // 16B-aligned rows; ldmatrix conflict-free
    constexpr int A_HALVES = BM * LDSA;
    constexpr int B_HALVES = BN * LDSA;
    constexpr int STAGE_HALVES = A_HALVES + B_HALVES;
    constexpr int NSTAGE = 3;
    constexpr int MI = WM / 16;
    constexpr int NI = WN / 8;

    extern __shared__ __half smem[];

    A += (long long)blockIdx.z * sAz;
    B += (long long)blockIdx.z * sBz;
    C += (long long)blockIdx.z * sCz;

    const int bm = blockIdx.y * BM;
    const int bn = blockIdx.x * BN;
    const int tid  = threadIdx.x;
    const int wid  = tid >> 5;
    const int lane = tid & 31;
    const int wm = (wid / WARPS_N) * WM;
    const int wn = (wid % WARPS_N) * WN;
    const int g = lane >> 2;
    const int c = lane & 3;

    uint32_t smem_base = smem_u32(smem);

    const int a_row = (lane & 15);
    const int a_kof = (lane >> 4) << 3;
    const int b_row = ((lane >> 4) << 3) + (lane & 7);
    const int b_kof = ((lane >> 3) & 1) << 3;

    float acc[MI][NI][4];
    #pragma unroll
    for (int mi = 0; mi < MI; mi++)
        #pragma unroll
        for (int ni = 0; ni < NI; ni++)
            #pragma unroll
            for (int r = 0; r < 4; r++) acc[mi][ni][r] = 0.f;

    const int nIter = K / BK;

    auto load_tiles = [&](int stage, int k0) {
        uint32_t sA = smem_base + (uint32_t)(stage * STAGE_HALVES) * 2u;
        uint32_t sB = sA + (uint32_t)A_HALVES * 2u;
        #pragma unroll
        for (int i = tid; i < BM * (BK/8); i += THREADS) {
            int row = i / (BK/8);
            int kc  = (i % (BK/8)) * 8;
            cp16(sA + (uint32_t)(row * LDSA + kc) * 2u,
                 A + (size_t)(bm + row) * lda + k0 + kc);
        }
        #pragma unroll
        for (int i = tid; i < BN * (BK/8); i += THREADS) {
            int row = i / (BK/8);
            int kc  = (i % (BK/8)) * 8;
            cp16(sB + (uint32_t)(row * LDSA + kc) * 2u,
                 B + (size_t)(bn + row) * ldb + k0 + kc);
        }
        cp_commit();
    };

    load_tiles(0, 0);
    if (nIter > 1) load_tiles(1, BK);

    for (int it = 0; it < nIter; it++) {
        if (it + 2 < nIter) { cp_wait<1>(); } else { cp_wait<0>(); }
        __syncthreads();
        if (it + 2 < nIter) load_tiles((it + 2) % NSTAGE, (it + 2) * BK);

        const uint32_t sAb = smem_base + (uint32_t)((it % NSTAGE) * STAGE_HALVES) * 2u;
        const uint32_t sBb = sAb + (uint32_t)A_HALVES * 2u;

        #pragma unroll
        for (int kk = 0; kk < BK; kk += 16) {
            uint32_t af[MI][4], bf[NI][2];
            #pragma unroll
            for (int mi = 0; mi < MI; mi++) {
                uint32_t addr = sAb + (uint32_t)((wm + mi*16 + a_row) * LDSA
                                                 + kk + a_kof) * 2u;
                ldsm_x4(af[mi][0], af[mi][1], af[mi][2], af[mi][3], addr);
            }
            #pragma unroll
            for (int p = 0; p < NI/2; p++) {
                uint32_t addr = sBb + (uint32_t)((wn + p*16 + b_row) * LDSA
                                                 + kk + b_kof) * 2u;
                ldsm_x4(bf[2*p][0], bf[2*p][1], bf[2*p+1][0], bf[2*p+1][1], addr);
            }
            #pragma unroll
            for (int mi = 0; mi < MI; mi++)
                #pragma unroll
                for (int ni = 0; ni < NI; ni++)
                    mma_16816(acc[mi][ni], af[mi], bf[ni]);
        }
    }

    // ---- epilogue ----
    #pragma unroll
    for (int mi = 0; mi < MI; mi++) {
        #pragma unroll
        for (int ni = 0; ni < NI; ni++) {
            int row = bm + wm + mi*16 + g;
            int col = bn + wn + ni*8 + 2*c;
            float bx = 0.f, by = 0.f;
            if (EPI == 1 || EPI == 2 || EPI == 3 || EPI == 6) {
                bx = bias[col]; by = bias[col+1];
            }
            #pragma unroll
            for (int half_ = 0; half_ < 2; half_++) {
                int r = row + half_*8;
                float vx = acc[mi][ni][half_*2+0];
                float vy = acc[mi][ni][half_*2+1];
                if (EPI == 1 || EPI == 2 || EPI == 3 || EPI == 6) { vx += bx; vy += by; }
                if (EPI == 2) {
                    *(__half2*)(auxh + (size_t)r * ldc + col)
                        = __floats2half2_rn(gelu_exact(vx), gelu_exact(vy));
                    continue;
                }
                if (EPI == 3) {
                    int l = r >> 3, b = r & 7;
                    int which = col >> 10;
                    int e = col & 1023;
                    int h = e >> 6, d = e & 63;
                    int bh = b * HH + h;
                    if (which == 0) { vx *= 0.125f; vy *= 0.125f; }
                    if (which < 2) {
                        __half2* P = (__half2*)(auxh + (size_t)which * QSZ
                                                + ((size_t)bh * LSEQ + l) * HD + d);
                        *P = __floats2half2_rn(vx, vy);
                    } else {
                        __half* Pv = auxh + 2 * QSZ + ((size_t)bh * HD + d) * LSEQ + l;
                        Pv[0]    = __float2half_rn(vx);
                        Pv[LSEQ] = __float2half_rn(vy);
                    }
                    continue;
                }
                if (EPI == 4) {
                    __half2 o2 = *(const __half2*)((const __half*)C
                                                   + (size_t)r * ldc + col);
                    float2 o = __half22float2(o2);
                    int l = blockIdx.z;
                    int b = r >> 4, h = r & 15;   // r = bh
                    __half2* P = (__half2*)(auxh + ((size_t)(l * BB + b) * EE)
                                            + h * HD + col);
                    *P = __floats2half2_rn(vx + o.x, vy + o.y);
                    continue;
                }
                if (EPI == 5 || EPI == 6) {
                    __half* Ch = (__half*)C;
                    *(__half2*)(Ch + (size_t)r * ldc + col)
                        = __floats2half2_rn(vx, vy);
                    continue;
                }
                float2* Cp = (float2*)(C + (size_t)r * ldc + col);
                if (ACCUM) {
                    float2 o = *Cp;
                    vx += o.x; vy += o.y;
                }
                *Cp = make_float2(vx, vy);
            }
        }
    }
}

// ============ fused pt-score accumulate + softmax (2-stage BK=32, as in R14) ============
__global__ void __launch_bounds__(512, 1)
score_pt_softmax(const __half* __restrict__ Qm, const __half* __restrict__ PT,
                 const __half* __restrict__ S, __half* __restrict__ W)
{
    constexpr int BM = 64, BN = 512, BK = 32, LDSA = 40;
    constexpr int A_HALVES = BM * LDSA;
    constexpr int B_HALVES = BN * LDSA;
    constexpr int STAGE = A_HALVES + B_HALVES;
    constexpr int MI = 2, NI = 8, WARPS_N = 8;

    extern __shared__ __half smem[];
    __shared__ float redmx[BM][WARPS_N];
    __shared__ float redsm[BM][WARPS_N];

    const int l  = blockIdx.y;
    const int bm = blockIdx.x * BM;
    const int tid  = threadIdx.x;
    const int wid  = tid >> 5;
    const int lane = tid & 31;
    const int wm = (wid / WARPS_N) * 32;
    const int wn = (wid % WARPS_N) * 64;
    const int wnx = wid % WARPS_N;
    const int g = lane >> 2, c = lane & 3;

    uint32_t smem_base = smem_u32(smem);
    const int a_row = (lane & 15);
    const int a_kof = (lane >> 4) << 3;
    const int b_row = ((lane >> 4) << 3) + (lane & 7);
    const int b_kof = ((lane >> 3) & 1) << 3;

    auto load_tiles = [&](int stage, int k0) {
        uint32_t sA = smem_base + (uint32_t)(stage * STAGE) * 2u;
        uint32_t sB = sA + (uint32_t)A_HALVES * 2u;
        #pragma unroll
        for (int i = tid; i < BM * (BK/8); i += 512) {
            int row = i >> 2; int kc = (i & 3) * 8;
            cp16(sA + (uint32_t)(row * LDSA + kc) * 2u,
                 Qm + ((size_t)(bm + row) * LSEQ + l) * HD + k0 + kc);
        }
        #pragma unroll
        for (int i = tid; i < BN * (BK/8); i += 512) {
            int row = i >> 2; int kc = (i & 3) * 8;
            cp16(sB + (uint32_t)(row * LDSA + kc) * 2u,
                 PT + ((size_t)l * LSEQ + row) * HD + k0 + kc);
        }
        cp_commit();
    };

    float acc[MI][NI][4];
    #pragma unroll
    for (int mi = 0; mi < MI; mi++)
        #pragma unroll
        for (int ni = 0; ni < NI; ni++)
            #pragma unroll
            for (int r = 0; r < 4; r++) acc[mi][ni][r] = 0.f;

    load_tiles(0, 0);
    load_tiles(1, BK);

    #pragma unroll
    for (int it = 0; it < 2; it++) {
        if (it == 0) { cp_wait<1>(); } else { cp_wait<0>(); }
        __syncthreads();
        const uint32_t sAb = smem_base + (uint32_t)(it * STAGE) * 2u;
        const uint32_t sBb = sAb + (uint32_t)A_HALVES * 2u;
        #pragma unroll
        for (int kk = 0; kk < BK; kk += 16) {
            uint32_t af[MI][4], bf[NI][2];
            #pragma unroll
            for (int mi = 0; mi < MI; mi++) {
                uint32_t addr = sAb + (uint32_t)((wm + mi*16 + a_row) * LDSA
                                                 + kk + a_kof) * 2u;
                ldsm_x4(af[mi][0], af[mi][1], af[mi][2], af[mi][3], addr);
            }
            #pragma unroll
            for (int p = 0; p < NI/2; p++) {
                uint32_t addr = sBb + (uint32_t)((wn + p*16 + b_row) * LDSA
                                                 + kk + b_kof) * 2u;
                ldsm_x4(bf[2*p][0], bf[2*p][1], bf[2*p+1][0], bf[2*p+1][1], addr);
            }
            #pragma unroll
            for (int mi = 0; mi < MI; mi++)
                #pragma unroll
                for (int ni = 0; ni < NI; ni++)
                    mma_16816(acc[mi][ni], af[mi], bf[ni]);
        }
    }

    // ---- add S (QK^T, half) ----
    #pragma unroll
    for (int mi = 0; mi < MI; mi++)
        #pragma unroll
        for (int half_ = 0; half_ < 2; half_++) {
            int rl = wm + mi*16 + g + half_*8;
            const __half* Sp = S + ((size_t)(bm + rl) * LSEQ + l) * LSEQ;
            #pragma unroll
            for (int ni = 0; ni < NI; ni++) {
                float2 o = __half22float2(
                    *(const __half2*)(Sp + wn + ni*8 + 2*c));
                acc[mi][ni][half_*2+0] += o.x;
                acc[mi][ni][half_*2+1] += o.y;
            }
        }

    // ---- row max ----
    #pragma unroll
    for (int mi = 0; mi < MI; mi++)
        #pragma unroll
        for (int half_ = 0; half_ < 2; half_++) {
            float m = -1e30f;
            #pragma unroll
            for (int ni = 0; ni < NI; ni++) {
                m = fmaxf(m, acc[mi][ni][half_*2+0]);
                m = fmaxf(m, acc[mi][ni][half_*2+1]);
            }
            m = fmaxf(m, __shfl_xor_sync(0xffffffffu, m, 1));
            m = fmaxf(m, __shfl_xor_sync(0xffffffffu, m, 2));
            if (c == 0) redmx[wm + mi*16 + g + half_*8][wnx] = m;
        }
    __syncthreads();

    // ---- exp + row sum ----
    #pragma unroll
    for (int mi = 0; mi < MI; mi++)
        #pragma unroll
        for (int half_ = 0; half_ < 2; half_++) {
            int rl = wm + mi*16 + g + half_*8;
            float m = redmx[rl][0];
            #pragma unroll
            for (int w = 1; w < WARPS_N; w++) m = fmaxf(m, redmx[rl][w]);
            float s = 0.f;
            #pragma unroll
            for (int ni = 0; ni < NI; ni++) {
                float vx = __expf(acc[mi][ni][half_*2+0] - m);
                float vy = __expf(acc[mi][ni][half_*2+1] - m);
                acc[mi][ni][half_*2+0] = vx;
                acc[mi][ni][half_*2+1] = vy;
                s += vx + vy;
            }
            s += __shfl_xor_sync(0xffffffffu, s, 1);
            s += __shfl_xor_sync(0xffffffffu, s, 2);
            if (c == 0) redsm[rl][wnx] = s;
        }
    __syncthreads();

    // ---- scale + write half ----
    #pragma unroll
    for (int mi = 0; mi < MI; mi++)
        #pragma unroll
        for (int half_ = 0; half_ < 2; half_++) {
            int rl = wm + mi*16 + g + half_*8;
            float s = 0.f;
            #pragma unroll
            for (int w = 0; w < WARPS_N; w++) s += redsm[rl][w];
            float inv = 1.0f / s;
            __half* Wp = W + ((size_t)(bm + rl) * LSEQ + l) * LSEQ;
            #pragma unroll
            for (int ni = 0; ni < NI; ni++) {
                *(__half2*)(Wp + wn + ni*8 + 2*c) =
                    __floats2half2_rn(acc[mi][ni][half_*2+0] * inv,
                                      acc[mi][ni][half_*2+1] * inv);
            }
        }
}

// ---------------- fused pt build: PTh[l,s,d] = half(pos+typ), PTt[l,d,s] ----------------
__global__ void pt_build_kernel(const float4* __restrict__ pos,
                                const float4* __restrict__ typ,
                                __half* __restrict__ PTh, __half* __restrict__ PTt)
{
    __shared__ __half tile[64][72];
    int l = blockIdx.x;
    int t = threadIdx.x;   // 256
    for (int st = 0; st < 8; st++) {
        for (int i = t; i < 1024; i += 256) {
            int s = i >> 4, c4 = i & 15;
            size_t idx = (((size_t)l * LSEQ + st*64 + s) * HD >> 2) + c4;
            float4 a = pos[idx], b = typ[idx];
            __half2 h0 = __floats2half2_rn(a.x + b.x, a.y + b.y);
            __half2 h1 = __floats2half2_rn(a.z + b.z, a.w + b.w);
            __half2* ph = (__half2*)(PTh + ((size_t)l * LSEQ + st*64 + s) * HD + c4*4);
            ph[0] = h0; ph[1] = h1;
            *(__half2*)&tile[s][c4*4]     = h0;
            *(__half2*)&tile[s][c4*4 + 2] = h1;
        }
        __syncthreads();
        for (int i = t; i < 64 * 32; i += 256) {
            int d = i >> 5;
            int s2 = (i & 31) * 2;
            __half2 h = __halves2half2(tile[s2][d], tile[s2+1][d]);
            *(__half2*)(PTt + ((size_t)l * HD + d) * LSEQ + st*64 + s2) = h;
        }
        __syncthreads();
    }
}

// ---------------- fp32 -> half ----------------
__global__ void f2h_kernel(const float4* __restrict__ a, __half* __restrict__ o, int n4)
{
    int i = blockIdx.x * blockDim.x + threadIdx.x;
    if (i < n4) {
        float4 x = a[i];
        __half2* p = (__half2*)(o + (size_t)i * 4);
        p[0] = __floats2half2_rn(x.x, x.y);
        p[1] = __floats2half2_rn(x.z, x.w);
    }
}

// ---------------- LN(residual): X fp32 + Y half; exact fp32 out + optional half copy ----------------
__global__ void ln_res_kernel(const float* __restrict__ X, const __half* __restrict__ Yh,
                              const float* __restrict__ g, const float* __restrict__ be,
                              float* __restrict__ O, __half* __restrict__ Oh)
{
    int row = blockIdx.x;
    int t = threadIdx.x;
    const float4* x4 = (const float4*)(X + (size_t)row * EE);
    const __half2* y2 = (const __half2*)(Yh + (size_t)row * EE);
    float4 a = x4[t];
    float2 b0 = __half22float2(y2[t*2]);
    float2 b1 = __half22float2(y2[t*2+1]);
    float4 v = make_float4(a.x+b0.x, a.y+b0.y, a.z+b1.x, a.w+b1.y);
    float s = v.x + v.y + v.z + v.w;
    float q = v.x*v.x + v.y*v.y + v.z*v.z + v.w*v.w;
    __shared__ float sh_s[8], sh_q[8];
    #pragma unroll
    for (int o = 16; o; o >>= 1) {
        s += __shfl_xor_sync(0xffffffffu, s, o);
        q += __shfl_xor_sync(0xffffffffu, q, o);
    }
    int wid = t >> 5, lane = t & 31;
    if (!lane) { sh_s[wid] = s; sh_q[wid] = q; }
    __syncthreads();
    if (t < 32) {
        s = (lane < 8) ? sh_s[lane] : 0.f;
        q = (lane < 8) ? sh_q[lane] : 0.f;
        #pragma unroll
        for (int o = 4; o; o >>= 1) {
            s += __shfl_xor_sync(0xffffffffu, s, o);
            q += __shfl_xor_sync(0xffffffffu, q, o);
        }
        if (!lane) { sh_s[0] = s; sh_q[0] = q; }
    }
    __syncthreads();
    float mean = sh_s[0] * (1.f/EE);
    float var  = sh_q[0] * (1.f/EE) - mean * mean;
    float r = rsqrtf(var + 1e-5f);
    float4 gg = ((const float4*)g)[t];
    float4 bb = ((const float4*)be)[t];
    float4 o;
    o.x = (v.x - mean) * r * gg.x + bb.x;
    o.y = (v.y - mean) * r * gg.y + bb.y;
    o.z = (v.z - mean) * r * gg.z + bb.z;
    o.w = (v.w - mean) * r * gg.w + bb.w;
    ((float4*)(O + (size_t)row * EE))[t] = o;
    if (Oh) {
        __half2* p = (__half2*)(Oh + (size_t)row * EE + t * 4);
        p[0] = __floats2half2_rn(o.x, o.y);
        p[1] = __floats2half2_rn(o.z, o.w);
    }
}

// ---------------- launch ----------------
static void* symv(const void* devSymbol) {
    void* p = nullptr;
    cudaGetSymbolAddress(&p, devSymbol);
    return p;
}

#define SMEM_B64_128x128 (3 * (128*72 + 128*72) * 2)   // 110592
#define SMEM_B32_128x128 (3 * (128*40 + 128*40) * 2)   // 61440
#define SMEM_B64_128x64  (3 * (128*72 +  64*72) * 2)   // 82944
#define SMEM_SS          (2 * (64*40 + 512*40) * 2)    // 92160

extern "C" void kernel_launch(void* const* d_in, const int* in_sizes, int n_in,
                              void* d_out, int out_size)
{
    const float* src = (const float*)d_in[0];
    const float* pos = (const float*)d_in[1];
    const float* typ = (const float*)d_in[2];
    const float* Wi  = (const float*)d_in[3];
    const float* bi  = (const float*)d_in[4];
    const float* Wo  = (const float*)d_in[5];
    const float* bo  = (const float*)d_in[6];
    const float* W1  = (const float*)d_in[7];
    const float* b1  = (const float*)d_in[8];
    const float* W2  = (const float*)d_in[9];
    const float* b2  = (const float*)d_in[10];
    const float* g1  = (const float*)d_in[11];
    const float* be1 = (const float*)d_in[12];
    const float* g2  = (const float*)d_in[13];
    const float* be2 = (const float*)d_in[14];
    float* out = (float*)d_out;

    __half* PTh  = (__half*)symv(g_PTh);
    __half* PTt  = (__half*)symv(g_PTt);
    __half* QKVh = (__half*)symv(g_QKVh);
    __half* Q = QKVh, *K = QKVh + QSZ, *Vt = QKVh + 2*QSZ;
    __half* Sh   = (__half*)symv(g_Sh);
    __half* Wh   = (__half*)symv(g_Wh);
    __half* AOh  = (__half*)symv(g_AOh);
    __half* AL   = (__half*)symv(g_ALh);
    __half* Yh   = (__half*)symv(g_Yh);
    float*  X1   = (float*)symv(g_X14);
    __half* X1h  = (__half*)symv(g_X1h);
    float*  X    = (float*)symv(g_X4);
    __half* Xh   = (__half*)symv(g_Xh);
    __half* Hh   = (__half*)symv(g_Hh);
    __half* Wih  = (__half*)symv(g_Wih);
    __half* Woh  = (__half*)symv(g_Woh);
    __half* W1h  = (__half*)symv(g_W1h);
    __half* W2h  = (__half*)symv(g_W2h);

    static bool attrs_done = false;
    if (!attrs_done) {
        cudaFuncSetAttribute(hgemm<128,128,64,32,64,3,false>,
                             cudaFuncAttributeMaxDynamicSharedMemorySize, SMEM_B64_128x128);
        cudaFuncSetAttribute(hgemm<128,128,64,32,32,5,false>,
                             cudaFuncAttributeMaxDynamicSharedMemorySize, SMEM_B32_128x128);
        cudaFuncSetAttribute(hgemm<128,128,64,32,64,6,false>,
                             cudaFuncAttributeMaxDynamicSharedMemorySize, SMEM_B64_128x128);
        cudaFuncSetAttribute(hgemm<128,128,64,32,64,2,false>,
                             cudaFuncAttributeMaxDynamicSharedMemorySize, SMEM_B64_128x128);
        cudaFuncSetAttribute(hgemm<128,64,32,32,64,5,false>,
                             cudaFuncAttributeMaxDynamicSharedMemorySize, SMEM_B64_128x64);
        cudaFuncSetAttribute(hgemm<128,64,32,32,64,4,false>,
                             cudaFuncAttributeMaxDynamicSharedMemorySize, SMEM_B64_128x64);
        cudaFuncSetAttribute(score_pt_softmax,
                             cudaFuncAttributeMaxDynamicSharedMemorySize, SMEM_SS);
        attrs_done = true;
    }

    // one-time conversions / fused pt build (R14 layout: separate launches)
    pt_build_kernel<<<LSEQ, 256>>>((const float4*)pos, (const float4*)typ, PTh, PTt);
    f2h_kernel<<<(NLAY*3*EE*EE/4)/256, 256>>>((const float4*)Wi, Wih, NLAY*3*EE*EE/4);
    f2h_kernel<<<(NLAY*EE*EE/4)/256,   256>>>((const float4*)Wo, Woh, NLAY*EE*EE/4);
    f2h_kernel<<<(NLAY*DFF*EE/4)/256,  256>>>((const float4*)W1, W1h, NLAY*DFF*EE/4);
    f2h_kernel<<<(NLAY*EE*DFF/4)/256,  256>>>((const float4*)W2, W2h, NLAY*EE*DFF/4);
    f2h_kernel<<<(MROWS*EE/4)/256,     256>>>((const float4*)src, Xh, MROWS*EE/4);

    const float* x = src;     // exact residual input
    for (int l = 0; l < NLAY; l++) {
        // 1) QKV GEMM (BK=64) + fused split epilogue -> Q|K [bh,l,d], V [bh,d,s]
        hgemm<128,128,64,32,64,3,false><<<dim3(24,32,1), 256, SMEM_B64_128x128>>>(
            Xh, EE, 0, Wih + (size_t)l*3*EE*EE, EE, 0,
            nullptr, 0, 0, bi + (size_t)l*3*EE, QKVh, MROWS, 3*EE, EE);

        // 2) Sh = half(Q @ K^T)  (batched over bh) — K=64, BK=32 keeps 2-iter overlap
        hgemm<128,128,64,32,32,5,false><<<dim3(4,4,BHN), 256, SMEM_B32_128x128>>>(
            Q, HD, (long long)LSEQ*HD, K, HD, (long long)LSEQ*HD,
            (float*)Sh, LSEQ, (long long)LSEQ*LSEQ/2, nullptr, nullptr,
            LSEQ, LSEQ, HD);

        // 3+4) fused: Wh = softmax(Sh + Q @ PT^T) per row (2-stage BK=32)
        score_pt_softmax<<<dim3(2, LSEQ), 512, SMEM_SS>>>(Q, PTh, Sh, Wh);

        // 5) AOh = half(Wh @ Vt^T)  (K=512, BK=64)
        hgemm<128,64,32,32,64,5,false><<<dim3(1,4,BHN), 256, SMEM_B64_128x64>>>(
            Wh, LSEQ, (long long)LSEQ*LSEQ, Vt, LSEQ, (long long)HD*LSEQ,
            (float*)AOh, HD, (long long)LSEQ*HD/2, nullptr, nullptr,
            LSEQ, HD, LSEQ);

        // 6) AL[l,b,e] = half(AOh + Wh[:,l,:] @ PTt[l]^T), fused reorder (BK=64)
        hgemm<128,64,32,32,64,4,false><<<dim3(1,1,LSEQ), 256, SMEM_B64_128x64>>>(
            Wh, LSEQ*LSEQ, (long long)LSEQ,
            PTt, LSEQ, (long long)HD*LSEQ,
            (float*)AOh, LSEQ*HD, (long long)HD/2,
            nullptr, AL, BHN, HD, LSEQ);

        // 7) Yh = half(AL @ Wo^T + bo)  (BK=64)
        hgemm<128,128,64,32,64,6,false><<<dim3(8,32,1), 256, SMEM_B64_128x128>>>(
            AL, EE, 0, Woh + (size_t)l*EE*EE, EE, 0,
            (float*)Yh, EE, 0, bo + (size_t)l*EE, nullptr, MROWS, EE, EE);

        // 8) X1 = LN(x + Yh)  (exact) + X1h (half)
        ln_res_kernel<<<MROWS, 256>>>(x, Yh, g1 + (size_t)l*EE, be1 + (size_t)l*EE, X1, X1h);

        // 9) Hh = half(gelu(X1h @ W1^T + b1))  (BK=64)
        hgemm<128,128,64,32,64,2,false><<<dim3(32,32,1), 256, SMEM_B64_128x128>>>(
            X1h, EE, 0, W1h + (size_t)l*DFF*EE, EE, 0,
            nullptr, DFF, 0, b1 + (size_t)l*DFF, Hh, MROWS, DFF, EE);

        // 10) Yh = half(Hh @ W2^T + b2)  (BK=64)
        hgemm<128,128,64,32,64,6,false><<<dim3(8,32,1), 256, SMEM_B64_128x128>>>(
            Hh, DFF, 0, W2h + (size_t)l*EE*DFF, DFF, 0,
            (float*)Yh, EE, 0, b2 + (size_t)l*EE, nullptr, MROWS, EE, DFF);

        // 11) next = LN(X1 + Yh); last layer -> d_out
        float*  xo  = (l == NLAY-1) ? out : X;
        __half* xoh = (l == NLAY-1) ? nullptr : Xh;
        ln_res_kernel<<<MROWS, 256>>>(X1, Yh, g2 + (size_t)l*EE, be2 + (size_t)l*EE, xo, xoh);

        x = X;
    }
}

// round 17
// speedup vs baseline: 1.0591x; 1.0152x over previous
#include <cuda_runtime.h>
#include <cuda_fp16.h>
#include <math.h>
#include <stdint.h>

// ---------------- problem constants ----------------
#define LSEQ 512
#define BB   8
#define EE   1024
#define HH   16
#define HD   64
#define NLAY 2
#define DFF  4096
#define MROWS (LSEQ*BB)          // 4096
#define BHN  (BB*HH)             // 128
#define QSZ  ((size_t)BHN*LSEQ*HD)
#define PT_ELEMS ((size_t)LSEQ*LSEQ*HD)

// ---------------- scratch ----------------
__device__ uint4  g_PTh [PT_ELEMS/8];
__device__ uint4  g_PTt [PT_ELEMS/8];
__device__ uint4  g_QKVh[3*QSZ/8];
__device__ uint4  g_Sh  [(size_t)BHN*LSEQ*LSEQ/8];
__device__ uint4  g_Wh  [(size_t)BHN*LSEQ*LSEQ/8];
__device__ uint4  g_AOh [(size_t)BHN*LSEQ*HD/8];
__device__ uint4  g_ALh [(size_t)MROWS*EE/8];
__device__ uint4  g_Yh  [(size_t)MROWS*EE/8];
__device__ float4 g_X14 [(size_t)MROWS*EE/4];
__device__ uint4  g_X1h [(size_t)MROWS*EE/8];
__device__ float4 g_X4  [(size_t)MROWS*EE/4];
__device__ uint4  g_Xh  [(size_t)MROWS*EE/8];
__device__ uint4  g_Hh  [(size_t)MROWS*DFF/8];
__device__ uint4  g_Wih [(size_t)NLAY*3*EE*EE/8];
__device__ uint4  g_Woh [(size_t)NLAY*EE*EE/8];
__device__ uint4  g_W1h [(size_t)NLAY*DFF*EE/8];
__device__ uint4  g_W2h [(size_t)NLAY*EE*DFF/8];

__device__ __forceinline__ float gelu_exact(float x) {
    return 0.5f * x * (1.0f + erff(x * 0.70710678118654752f));
}
__device__ __forceinline__ void cp16(uint32_t saddr, const void* gaddr) {
    asm volatile("cp.async.cg.shared.global [%0], [%1], 16;\n"
                 :: "r"(saddr), "l"(gaddr));
}
__device__ __forceinline__ void cp_commit() {
    asm volatile("cp.async.commit_group;\n");
}
template<int N>
__device__ __forceinline__ void cp_wait() {
    asm volatile("cp.async.wait_group %0;\n" :: "n"(N));
}
__device__ __forceinline__ uint32_t smem_u32(const void* p) {
    uint32_t a;
    asm("{ .reg .u64 t; cvta.to.shared.u64 t, %1; cvt.u32.u64 %0, t; }"
        : "=r"(a) : "l"(p));
    return a;
}
__device__ __forceinline__ void ldsm_x4(uint32_t& r0, uint32_t& r1,
                                        uint32_t& r2, uint32_t& r3, uint32_t saddr)
{
    asm volatile("ldmatrix.sync.aligned.m8n8.x4.shared.b16 {%0,%1,%2,%3}, [%4];"
                 : "=r"(r0), "=r"(r1), "=r"(r2), "=r"(r3) : "r"(saddr));
}
__device__ __forceinline__ void mma_16816(float* acc, const uint32_t* a, const uint32_t* b)
{
    asm volatile(
        "mma.sync.aligned.m16n8k16.row.col.f32.f16.f16.f32 "
        "{%0,%1,%2,%3}, {%4,%5,%6,%7}, {%8,%9}, {%0,%1,%2,%3};\n"
        : "+f"(acc[0]), "+f"(acc[1]), "+f"(acc[2]), "+f"(acc[3])
        : "r"(a[0]), "r"(a[1]), "r"(a[2]), "r"(a[3]), "r"(b[0]), "r"(b[1]));
}

// ---------------- FP16 tensor-core GEMM (NT), cp.async 3-stage, BK=64 ----------------
// EPI: 0 fp32 C (ACCUM opt); 1 +bias fp32 C; 2 +bias,gelu -> half auxh;
//      3 qkv split half -> auxh; 4 read half C, add, half -> auxh [l,b,e];
//      5 plain half -> C-as-half; 6 +bias, half -> C-as-half (sCz FLOAT units).
template<int BM, int BN, int WM, int WN, int EPI, bool ACCUM>
__global__ void __launch_bounds__((BM/WM)*(BN/WN)*32, 2)
hgemm(const __half* __restrict__ A, int lda, long long sAz,
      const __half* __restrict__ B, int ldb, long long sBz,
      float* __restrict__ C, int ldc, long long sCz,
      const float* __restrict__ bias, __half* __restrict__ auxh,
      int M, int N, int K)
{
    constexpr int BK = 64;
    constexpr int WARPS_M = BM / WM;
    constexpr int WARPS_N = BN / WN;
    constexpr int THREADS = WARPS_M * WARPS_N * 32;
    constexpr int LDSA = BK + 8;            // 72 halves = 144B rows; conflict-free
    constexpr int A_HALVES = BM * LDSA;
    constexpr int B_HALVES = BN * LDSA;
    constexpr int STAGE_HALVES = A_HALVES + B_HALVES;
    constexpr int NSTAGE = 3;
    constexpr int MI = WM / 16;
    constexpr int NI = WN / 8;

    extern __shared__ __half smem[];

    A += (long long)blockIdx.z * sAz;
    B += (long long)blockIdx.z * sBz;
    C += (long long)blockIdx.z * sCz;

    const int bm = blockIdx.y * BM;
    const int bn = blockIdx.x * BN;
    const int tid  = threadIdx.x;
    const int wid  = tid >> 5;
    const int lane = tid & 31;
    const int wm = (wid / WARPS_N) * WM;
    const int wn = (wid % WARPS_N) * WN;
    const int g = lane >> 2;
    const int c = lane & 3;

    uint32_t smem_base = smem_u32(smem);

    const int a_row = (lane & 15);
    const int a_kof = (lane >> 4) << 3;
    const int b_row = ((lane >> 4) << 3) + (lane & 7);
    const int b_kof = ((lane >> 3) & 1) << 3;

    float acc[MI][NI][4];
    #pragma unroll
    for (int mi = 0; mi < MI; mi++)
        #pragma unroll
        for (int ni = 0; ni < NI; ni++)
            #pragma unroll
            for (int r = 0; r < 4; r++) acc[mi][ni][r] = 0.f;

    const int nIter = K / BK;

    auto load_tiles = [&](int stage, int k0) {
        uint32_t sA = smem_base + (uint32_t)(stage * STAGE_HALVES) * 2u;
        uint32_t sB = sA + (uint32_t)A_HALVES * 2u;
        #pragma unroll
        for (int i = tid; i < BM * (BK/8); i += THREADS) {
            int row = i / (BK/8);
            int kc  = (i % (BK/8)) * 8;
            cp16(sA + (uint32_t)(row * LDSA + kc) * 2u,
                 A + (size_t)(bm + row) * lda + k0 + kc);
        }
        #pragma unroll
        for (int i = tid; i < BN * (BK/8); i += THREADS) {
            int row = i / (BK/8);
            int kc  = (i % (BK/8)) * 8;
            cp16(sB + (uint32_t)(row * LDSA + kc) * 2u,
                 B + (size_t)(bn + row) * ldb + k0 + kc);
        }
        cp_commit();
    };

    load_tiles(0, 0);
    if (nIter > 1) load_tiles(1, BK);

    for (int it = 0; it < nIter; it++) {
        if (it + 2 < nIter) { cp_wait<1>(); } else { cp_wait<0>(); }
        __syncthreads();
        if (it + 2 < nIter) load_tiles((it + 2) % NSTAGE, (it + 2) * BK);

        const uint32_t sAb = smem_base + (uint32_t)((it % NSTAGE) * STAGE_HALVES) * 2u;
        const uint32_t sBb = sAb + (uint32_t)A_HALVES * 2u;

        #pragma unroll
        for (int kk = 0; kk < BK; kk += 16) {
            uint32_t af[MI][4], bf[NI][2];
            #pragma unroll
            for (int mi = 0; mi < MI; mi++) {
                uint32_t addr = sAb + (uint32_t)((wm + mi*16 + a_row) * LDSA
                                                 + kk + a_kof) * 2u;
                ldsm_x4(af[mi][0], af[mi][1], af[mi][2], af[mi][3], addr);
            }
            #pragma unroll
            for (int p = 0; p < NI/2; p++) {
                uint32_t addr = sBb + (uint32_t)((wn + p*16 + b_row) * LDSA
                                                 + kk + b_kof) * 2u;
                ldsm_x4(bf[2*p][0], bf[2*p][1], bf[2*p+1][0], bf[2*p+1][1], addr);
            }
            #pragma unroll
            for (int mi = 0; mi < MI; mi++)
                #pragma unroll
                for (int ni = 0; ni < NI; ni++)
                    mma_16816(acc[mi][ni], af[mi], bf[ni]);
        }
    }

    // ---- epilogue ----
    #pragma unroll
    for (int mi = 0; mi < MI; mi++) {
        #pragma unroll
        for (int ni = 0; ni < NI; ni++) {
            int row = bm + wm + mi*16 + g;
            int col = bn + wn + ni*8 + 2*c;
            float bx = 0.f, by = 0.f;
            if (EPI == 1 || EPI == 2 || EPI == 3 || EPI == 6) {
                bx = bias[col]; by = bias[col+1];
            }
            #pragma unroll
            for (int half_ = 0; half_ < 2; half_++) {
                int r = row + half_*8;
                float vx = acc[mi][ni][half_*2+0];
                float vy = acc[mi][ni][half_*2+1];
                if (EPI == 1 || EPI == 2 || EPI == 3 || EPI == 6) { vx += bx; vy += by; }
                if (EPI == 2) {
                    *(__half2*)(auxh + (size_t)r * ldc + col)
                        = __floats2half2_rn(gelu_exact(vx), gelu_exact(vy));
                    continue;
                }
                if (EPI == 3) {
                    int l = r >> 3, b = r & 7;
                    int which = col >> 10;
                    int e = col & 1023;
                    int h = e >> 6, d = e & 63;
                    int bh = b * HH + h;
                    if (which == 0) { vx *= 0.125f; vy *= 0.125f; }
                    if (which < 2) {
                        __half2* P = (__half2*)(auxh + (size_t)which * QSZ
                                                + ((size_t)bh * LSEQ + l) * HD + d);
                        *P = __floats2half2_rn(vx, vy);
                    } else {
                        __half* Pv = auxh + 2 * QSZ + ((size_t)bh * HD + d) * LSEQ + l;
                        Pv[0]    = __float2half_rn(vx);
                        Pv[LSEQ] = __float2half_rn(vy);
                    }
                    continue;
                }
                if (EPI == 4) {
                    __half2 o2 = *(const __half2*)((const __half*)C
                                                   + (size_t)r * ldc + col);
                    float2 o = __half22float2(o2);
                    int l = blockIdx.z;
                    int b = r >> 4, h = r & 15;   // r = bh
                    __half2* P = (__half2*)(auxh + ((size_t)(l * BB + b) * EE)
                                            + h * HD + col);
                    *P = __floats2half2_rn(vx + o.x, vy + o.y);
                    continue;
                }
                if (EPI == 5 || EPI == 6) {
                    __half* Ch = (__half*)C;
                    *(__half2*)(Ch + (size_t)r * ldc + col)
                        = __floats2half2_rn(vx, vy);
                    continue;
                }
                float2* Cp = (float2*)(C + (size_t)r * ldc + col);
                if (ACCUM) {
                    float2 o = *Cp;
                    vx += o.x; vy += o.y;
                }
                *Cp = make_float2(vx, vy);
            }
        }
    }
}

// ============ fused pt-score accumulate + softmax (2-stage BK=32) ============
__global__ void __launch_bounds__(512, 1)
score_pt_softmax(const __half* __restrict__ Qm, const __half* __restrict__ PT,
                 const __half* __restrict__ S, __half* __restrict__ W)
{
    constexpr int BM = 64, BN = 512, BK = 32, LDSA = 40;
    constexpr int A_HALVES = BM * LDSA;
    constexpr int B_HALVES = BN * LDSA;
    constexpr int STAGE = A_HALVES + B_HALVES;
    constexpr int MI = 2, NI = 8, WARPS_N = 8;

    extern __shared__ __half smem[];
    __shared__ float redmx[BM][WARPS_N];
    __shared__ float redsm[BM][WARPS_N];

    const int l  = blockIdx.y;
    const int bm = blockIdx.x * BM;
    const int tid  = threadIdx.x;
    const int wid  = tid >> 5;
    const int lane = tid & 31;
    const int wm = (wid / WARPS_N) * 32;
    const int wn = (wid % WARPS_N) * 64;
    const int wnx = wid % WARPS_N;
    const int g = lane >> 2, c = lane & 3;

    uint32_t smem_base = smem_u32(smem);
    const int a_row = (lane & 15);
    const int a_kof = (lane >> 4) << 3;
    const int b_row = ((lane >> 4) << 3) + (lane & 7);
    const int b_kof = ((lane >> 3) & 1) << 3;

    auto load_tiles = [&](int stage, int k0) {
        uint32_t sA = smem_base + (uint32_t)(stage * STAGE) * 2u;
        uint32_t sB = sA + (uint32_t)A_HALVES * 2u;
        #pragma unroll
        for (int i = tid; i < BM * (BK/8); i += 512) {
            int row = i >> 2; int kc = (i & 3) * 8;
            cp16(sA + (uint32_t)(row * LDSA + kc) * 2u,
                 Qm + ((size_t)(bm + row) * LSEQ + l) * HD + k0 + kc);
        }
        #pragma unroll
        for (int i = tid; i < BN * (BK/8); i += 512) {
            int row = i >> 2; int kc = (i & 3) * 8;
            cp16(sB + (uint32_t)(row * LDSA + kc) * 2u,
                 PT + ((size_t)l * LSEQ + row) * HD + k0 + kc);
        }
        cp_commit();
    };

    float acc[MI][NI][4];
    #pragma unroll
    for (int mi = 0; mi < MI; mi++)
        #pragma unroll
        for (int ni = 0; ni < NI; ni++)
            #pragma unroll
            for (int r = 0; r < 4; r++) acc[mi][ni][r] = 0.f;

    load_tiles(0, 0);
    load_tiles(1, BK);

    #pragma unroll
    for (int it = 0; it < 2; it++) {
        if (it == 0) { cp_wait<1>(); } else { cp_wait<0>(); }
        __syncthreads();
        const uint32_t sAb = smem_base + (uint32_t)(it * STAGE) * 2u;
        const uint32_t sBb = sAb + (uint32_t)A_HALVES * 2u;
        #pragma unroll
        for (int kk = 0; kk < BK; kk += 16) {
            uint32_t af[MI][4], bf[NI][2];
            #pragma unroll
            for (int mi = 0; mi < MI; mi++) {
                uint32_t addr = sAb + (uint32_t)((wm + mi*16 + a_row) * LDSA
                                                 + kk + a_kof) * 2u;
                ldsm_x4(af[mi][0], af[mi][1], af[mi][2], af[mi][3], addr);
            }
            #pragma unroll
            for (int p = 0; p < NI/2; p++) {
                uint32_t addr = sBb + (uint32_t)((wn + p*16 + b_row) * LDSA
                                                 + kk + b_kof) * 2u;
                ldsm_x4(bf[2*p][0], bf[2*p][1], bf[2*p+1][0], bf[2*p+1][1], addr);
            }
            #pragma unroll
            for (int mi = 0; mi < MI; mi++)
                #pragma unroll
                for (int ni = 0; ni < NI; ni++)
                    mma_16816(acc[mi][ni], af[mi], bf[ni]);
        }
    }

    // ---- add S (QK^T, half) ----
    #pragma unroll
    for (int mi = 0; mi < MI; mi++)
        #pragma unroll
        for (int half_ = 0; half_ < 2; half_++) {
            int rl = wm + mi*16 + g + half_*8;
            const __half* Sp = S + ((size_t)(bm + rl) * LSEQ + l) * LSEQ;
            #pragma unroll
            for (int ni = 0; ni < NI; ni++) {
                float2 o = __half22float2(
                    *(const __half2*)(Sp + wn + ni*8 + 2*c));
                acc[mi][ni][half_*2+0] += o.x;
                acc[mi][ni][half_*2+1] += o.y;
            }
        }

    // ---- row max ----
    #pragma unroll
    for (int mi = 0; mi < MI; mi++)
        #pragma unroll
        for (int half_ = 0; half_ < 2; half_++) {
            float m = -1e30f;
            #pragma unroll
            for (int ni = 0; ni < NI; ni++) {
                m = fmaxf(m, acc[mi][ni][half_*2+0]);
                m = fmaxf(m, acc[mi][ni][half_*2+1]);
            }
            m = fmaxf(m, __shfl_xor_sync(0xffffffffu, m, 1));
            m = fmaxf(m, __shfl_xor_sync(0xffffffffu, m, 2));
            if (c == 0) redmx[wm + mi*16 + g + half_*8][wnx] = m;
        }
    __syncthreads();

    // ---- exp + row sum ----
    #pragma unroll
    for (int mi = 0; mi < MI; mi++)
        #pragma unroll
        for (int half_ = 0; half_ < 2; half_++) {
            int rl = wm + mi*16 + g + half_*8;
            float m = redmx[rl][0];
            #pragma unroll
            for (int w = 1; w < WARPS_N; w++) m = fmaxf(m, redmx[rl][w]);
            float s = 0.f;
            #pragma unroll
            for (int ni = 0; ni < NI; ni++) {
                float vx = __expf(acc[mi][ni][half_*2+0] - m);
                float vy = __expf(acc[mi][ni][half_*2+1] - m);
                acc[mi][ni][half_*2+0] = vx;
                acc[mi][ni][half_*2+1] = vy;
                s += vx + vy;
            }
            s += __shfl_xor_sync(0xffffffffu, s, 1);
            s += __shfl_xor_sync(0xffffffffu, s, 2);
            if (c == 0) redsm[rl][wnx] = s;
        }
    __syncthreads();

    // ---- scale + write half ----
    #pragma unroll
    for (int mi = 0; mi < MI; mi++)
        #pragma unroll
        for (int half_ = 0; half_ < 2; half_++) {
            int rl = wm + mi*16 + g + half_*8;
            float s = 0.f;
            #pragma unroll
            for (int w = 0; w < WARPS_N; w++) s += redsm[rl][w];
            float inv = 1.0f / s;
            __half* Wp = W + ((size_t)(bm + rl) * LSEQ + l) * LSEQ;
            #pragma unroll
            for (int ni = 0; ni < NI; ni++) {
                *(__half2*)(Wp + wn + ni*8 + 2*c) =
                    __floats2half2_rn(acc[mi][ni][half_*2+0] * inv,
                                      acc[mi][ni][half_*2+1] * inv);
            }
        }
}

// ---------------- fused pt build: PTh[l,s,d] = half(pos+typ), PTt[l,d,s] ----------------
__global__ void pt_build_kernel(const float4* __restrict__ pos,
                                const float4* __restrict__ typ,
                                __half* __restrict__ PTh, __half* __restrict__ PTt)
{
    __shared__ __half tile[64][72];
    int l = blockIdx.x;
    int t = threadIdx.x;   // 256
    for (int st = 0; st < 8; st++) {
        for (int i = t; i < 1024; i += 256) {
            int s = i >> 4, c4 = i & 15;
            size_t idx = (((size_t)l * LSEQ + st*64 + s) * HD >> 2) + c4;
            float4 a = pos[idx], b = typ[idx];
            __half2 h0 = __floats2half2_rn(a.x + b.x, a.y + b.y);
            __half2 h1 = __floats2half2_rn(a.z + b.z, a.w + b.w);
            __half2* ph = (__half2*)(PTh + ((size_t)l * LSEQ + st*64 + s) * HD + c4*4);
            ph[0] = h0; ph[1] = h1;
            *(__half2*)&tile[s][c4*4]     = h0;
            *(__half2*)&tile[s][c4*4 + 2] = h1;
        }
        __syncthreads();
        for (int i = t; i < 64 * 32; i += 256) {
            int d = i >> 5;
            int s2 = (i & 31) * 2;
            __half2 h = __halves2half2(tile[s2][d], tile[s2+1][d]);
            *(__half2*)(PTt + ((size_t)l * HD + d) * LSEQ + st*64 + s2) = h;
        }
        __syncthreads();
    }
}

// ---------------- fp32 -> half ----------------
__global__ void f2h_kernel(const float4* __restrict__ a, __half* __restrict__ o, int n4)
{
    int i = blockIdx.x * blockDim.x + threadIdx.x;
    if (i < n4) {
        float4 x = a[i];
        __half2* p = (__half2*)(o + (size_t)i * 4);
        p[0] = __floats2half2_rn(x.x, x.y);
        p[1] = __floats2half2_rn(x.z, x.w);
    }
}

// ---------------- LN(residual): X fp32 + Y half; exact fp32 out + optional half copy ----------------
__global__ void ln_res_kernel(const float* __restrict__ X, const __half* __restrict__ Yh,
                              const float* __restrict__ g, const float* __restrict__ be,
                              float* __restrict__ O, __half* __restrict__ Oh)
{
    int row = blockIdx.x;
    int t = threadIdx.x;
    const float4* x4 = (const float4*)(X + (size_t)row * EE);
    const __half2* y2 = (const __half2*)(Yh + (size_t)row * EE);
    float4 a = x4[t];
    float2 b0 = __half22float2(y2[t*2]);
    float2 b1 = __half22float2(y2[t*2+1]);
    float4 v = make_float4(a.x+b0.x, a.y+b0.y, a.z+b1.x, a.w+b1.y);
    float s = v.x + v.y + v.z + v.w;
    float q = v.x*v.x + v.y*v.y + v.z*v.z + v.w*v.w;
    __shared__ float sh_s[8], sh_q[8];
    #pragma unroll
    for (int o = 16; o; o >>= 1) {
        s += __shfl_xor_sync(0xffffffffu, s, o);
        q += __shfl_xor_sync(0xffffffffu, q, o);
    }
    int wid = t >> 5, lane = t & 31;
    if (!lane) { sh_s[wid] = s; sh_q[wid] = q; }
    __syncthreads();
    if (t < 32) {
        s = (lane < 8) ? sh_s[lane] : 0.f;
        q = (lane < 8) ? sh_q[lane] : 0.f;
        #pragma unroll
        for (int o = 4; o; o >>= 1) {
            s += __shfl_xor_sync(0xffffffffu, s, o);
            q += __shfl_xor_sync(0xffffffffu, q, o);
        }
        if (!lane) { sh_s[0] = s; sh_q[0] = q; }
    }
    __syncthreads();
    float mean = sh_s[0] * (1.f/EE);
    float var  = sh_q[0] * (1.f/EE) - mean * mean;
    float r = rsqrtf(var + 1e-5f);
    float4 gg = ((const float4*)g)[t];
    float4 bb = ((const float4*)be)[t];
    float4 o;
    o.x = (v.x - mean) * r * gg.x + bb.x;
    o.y = (v.y - mean) * r * gg.y + bb.y;
    o.z = (v.z - mean) * r * gg.z + bb.z;
    o.w = (v.w - mean) * r * gg.w + bb.w;
    ((float4*)(O + (size_t)row * EE))[t] = o;
    if (Oh) {
        __half2* p = (__half2*)(Oh + (size_t)row * EE + t * 4);
        p[0] = __floats2half2_rn(o.x, o.y);
        p[1] = __floats2half2_rn(o.z, o.w);
    }
}

// ---------------- launch ----------------
static void* symv(const void* devSymbol) {
    void* p = nullptr;
    cudaGetSymbolAddress(&p, devSymbol);
    return p;
}

#define SMEM_H128x128 (3 * (128*72 + 128*72) * 2)   // 110592
#define SMEM_H128x64  (3 * (128*72 +  64*72) * 2)   // 82944
#define SMEM_SS       (2 * (64*40 + 512*40) * 2)    // 92160

extern "C" void kernel_launch(void* const* d_in, const int* in_sizes, int n_in,
                              void* d_out, int out_size)
{
    const float* src = (const float*)d_in[0];
    const float* pos = (const float*)d_in[1];
    const float* typ = (const float*)d_in[2];
    const float* Wi  = (const float*)d_in[3];
    const float* bi  = (const float*)d_in[4];
    const float* Wo  = (const float*)d_in[5];
    const float* bo  = (const float*)d_in[6];
    const float* W1  = (const float*)d_in[7];
    const float* b1  = (const float*)d_in[8];
    const float* W2  = (const float*)d_in[9];
    const float* b2  = (const float*)d_in[10];
    const float* g1  = (const float*)d_in[11];
    const float* be1 = (const float*)d_in[12];
    const float* g2  = (const float*)d_in[13];
    const float* be2 = (const float*)d_in[14];
    float* out = (float*)d_out;

    __half* PTh  = (__half*)symv(g_PTh);
    __half* PTt  = (__half*)symv(g_PTt);
    __half* QKVh = (__half*)symv(g_QKVh);
    __half* Q = QKVh, *K = QKVh + QSZ, *Vt = QKVh + 2*QSZ;
    __half* Sh   = (__half*)symv(g_Sh);
    __half* Wh   = (__half*)symv(g_Wh);
    __half* AOh  = (__half*)symv(g_AOh);
    __half* AL   = (__half*)symv(g_ALh);
    __half* Yh   = (__half*)symv(g_Yh);
    float*  X1   = (float*)symv(g_X14);
    __half* X1h  = (__half*)symv(g_X1h);
    float*  X    = (float*)symv(g_X4);
    __half* Xh   = (__half*)symv(g_Xh);
    __half* Hh   = (__half*)symv(g_Hh);
    __half* Wih  = (__half*)symv(g_Wih);
    __half* Woh  = (__half*)symv(g_Woh);
    __half* W1h  = (__half*)symv(g_W1h);
    __half* W2h  = (__half*)symv(g_W2h);

    static bool attrs_done = false;
    static cudaStream_t s1 = nullptr;
    static cudaEvent_t evFork = nullptr, evJoin = nullptr;
    if (!attrs_done) {
        cudaFuncSetAttribute(hgemm<128,128,64,32,3,false>,
                             cudaFuncAttributeMaxDynamicSharedMemorySize, SMEM_H128x128);
        cudaFuncSetAttribute(hgemm<128,128,64,32,5,false>,
                             cudaFuncAttributeMaxDynamicSharedMemorySize, SMEM_H128x128);
        cudaFuncSetAttribute(hgemm<128,128,64,32,6,false>,
                             cudaFuncAttributeMaxDynamicSharedMemorySize, SMEM_H128x128);
        cudaFuncSetAttribute(hgemm<128,128,64,32,2,false>,
                             cudaFuncAttributeMaxDynamicSharedMemorySize, SMEM_H128x128);
        cudaFuncSetAttribute(hgemm<128,64,32,32,5,false>,
                             cudaFuncAttributeMaxDynamicSharedMemorySize, SMEM_H128x64);
        cudaFuncSetAttribute(hgemm<128,64,32,32,4,false>,
                             cudaFuncAttributeMaxDynamicSharedMemorySize, SMEM_H128x64);
        cudaFuncSetAttribute(score_pt_softmax,
                             cudaFuncAttributeMaxDynamicSharedMemorySize, SMEM_SS);
        cudaStreamCreateWithFlags(&s1, cudaStreamNonBlocking);
        cudaEventCreateWithFlags(&evFork, cudaEventDisableTiming);
        cudaEventCreateWithFlags(&evJoin, cudaEventDisableTiming);
        attrs_done = true;
    }

    // ---- preamble: fork weight conversions to side stream, pt build on main ----
    cudaEventRecord(evFork, 0);
    cudaStreamWaitEvent(s1, evFork, 0);
    f2h_kernel<<<(NLAY*3*EE*EE/4)/256, 256, 0, s1>>>((const float4*)Wi, Wih, NLAY*3*EE*EE/4);
    f2h_kernel<<<(NLAY*EE*EE/4)/256,   256, 0, s1>>>((const float4*)Wo, Woh, NLAY*EE*EE/4);
    f2h_kernel<<<(NLAY*DFF*EE/4)/256,  256, 0, s1>>>((const float4*)W1, W1h, NLAY*DFF*EE/4);
    f2h_kernel<<<(NLAY*EE*DFF/4)/256,  256, 0, s1>>>((const float4*)W2, W2h, NLAY*EE*DFF/4);
    cudaEventRecord(evJoin, s1);
    pt_build_kernel<<<LSEQ, 256>>>((const float4*)pos, (const float4*)typ, PTh, PTt);
    f2h_kernel<<<(MROWS*EE/4)/256, 256>>>((const float4*)src, Xh, MROWS*EE/4);
    cudaStreamWaitEvent(0, evJoin, 0);

    const float* x = src;     // exact residual input
    for (int l = 0; l < NLAY; l++) {
        // 1) QKV GEMM + fused split epilogue -> Q|K [bh,l,d], V [bh,d,s]
        hgemm<128,128,64,32,3,false><<<dim3(24,32,1), 256, SMEM_H128x128>>>(
            Xh, EE, 0, Wih + (size_t)l*3*EE*EE, EE, 0,
            nullptr, 0, 0, bi + (size_t)l*3*EE, QKVh, MROWS, 3*EE, EE);

        // 2) Sh = half(Q @ K^T)  (batched over bh)
        hgemm<128,128,64,32,5,false><<<dim3(4,4,BHN), 256, SMEM_H128x128>>>(
            Q, HD, (long long)LSEQ*HD, K, HD, (long long)LSEQ*HD,
            (float*)Sh, LSEQ, (long long)LSEQ*LSEQ/2, nullptr, nullptr,
            LSEQ, LSEQ, HD);

        // 3+4) fused: Wh = softmax(Sh + Q @ PT^T) per row (2-stage BK=32)
        score_pt_softmax<<<dim3(2, LSEQ), 512, SMEM_SS>>>(Q, PTh, Sh, Wh);

        // 5) AOh = half(Wh @ Vt^T)
        hgemm<128,64,32,32,5,false><<<dim3(1,4,BHN), 256, SMEM_H128x64>>>(
            Wh, LSEQ, (long long)LSEQ*LSEQ, Vt, LSEQ, (long long)HD*LSEQ,
            (float*)AOh, HD, (long long)LSEQ*HD/2, nullptr, nullptr,
            LSEQ, HD, LSEQ);

        // 6) AL[l,b,e] = half(AOh + Wh[:,l,:] @ PTt[l]^T), fused reorder
        hgemm<128,64,32,32,4,false><<<dim3(1,1,LSEQ), 256, SMEM_H128x64>>>(
            Wh, LSEQ*LSEQ, (long long)LSEQ,
            PTt, LSEQ, (long long)HD*LSEQ,
            (float*)AOh, LSEQ*HD, (long long)HD/2,
            nullptr, AL, BHN, HD, LSEQ);

        // 7) Yh = half(AL @ Wo^T + bo)
        hgemm<128,128,64,32,6,false><<<dim3(8,32,1), 256, SMEM_H128x128>>>(
            AL, EE, 0, Woh + (size_t)l*EE*EE, EE, 0,
            (float*)Yh, EE, 0, bo + (size_t)l*EE, nullptr, MROWS, EE, EE);

        // 8) X1 = LN(x + Yh)  (exact) + X1h (half)
        ln_res_kernel<<<MROWS, 256>>>(x, Yh, g1 + (size_t)l*EE, be1 + (size_t)l*EE, X1, X1h);

        // 9) Hh = half(gelu(X1h @ W1^T + b1))
        hgemm<128,128,64,32,2,false><<<dim3(32,32,1), 256, SMEM_H128x128>>>(
            X1h, EE, 0, W1h + (size_t)l*DFF*EE, EE, 0,
            nullptr, DFF, 0, b1 + (size_t)l*DFF, Hh, MROWS, DFF, EE);

        // 10) Yh = half(Hh @ W2^T + b2)
        hgemm<128,128,64,32,6,false><<<dim3(8,32,1), 256, SMEM_H128x128>>>(
            Hh, DFF, 0, W2h + (size_t)l*EE*DFF, DFF, 0,
            (float*)Yh, EE, 0, b2 + (size_t)l*EE, nullptr, MROWS, EE, DFF);

        // 11) next = LN(X1 + Yh); last layer -> d_out
        float*  xo  = (l == NLAY-1) ? out : X;
        __half* xoh = (l == NLAY-1) ? nullptr : Xh;
        ln_res_kernel<<<MROWS, 256>>>(X1, Yh, g2 + (size_t)l*EE, be2 + (size_t)l*EE, xo, xoh);

        x = X;
    }
}